// round 5
// baseline (speedup 1.0000x reference)
#include <cuda_runtime.h>
#include <cuda_bf16.h>
#include <math.h>
#include <stdint.h>
#include <stddef.h>

// Problem dims
#define Bsz 256
#define Ssz 512
#define Fdim 128
#define Hdim 128
#define G3  384   // 3*H

// Output layout (tuple flattened): h_enc, output, z, gamma, dis, dis_perm
#define OFF_HENC  ((size_t)0)
#define OFF_OUT   ((size_t)32768)                       // 256*128
#define OFF_Z     ((size_t)(32768 + 16777216))          // + 256*512*128
#define OFF_GAMMA ((size_t)(OFF_Z + 256*129))
#define OFF_DIS   ((size_t)(OFF_GAMMA + 256*4))
#define OFF_DISP  ((size_t)(OFF_DIS + 256*8*128))

// Scratch (device globals; no allocations allowed)
__device__ float g_Genc[(size_t)Ssz * Bsz * G3];    // [t][b][g]  192 MB
__device__ float g_Hdec[(size_t)Ssz * Bsz * Hdim];  // [i][b][j]   64 MB
__device__ float g_Henc[Bsz * Hdim];
__device__ float g_Mf[G3 * Hdim];
__device__ float g_bf[G3];
__device__ int   g_perm[8 * Bsz];                   // [k][pos] -> batch idx

__device__ __forceinline__ float sigf(float x) { return 1.0f / (1.0f + expf(-x)); }

// ---------------------------------------------------------------------------
// Threefry2x32 core (20 rounds, exact JAX constants)
// ---------------------------------------------------------------------------
__device__ __forceinline__ uint2 threefry(unsigned k0, unsigned k1,
                                          unsigned x0, unsigned x1) {
    unsigned ks2 = k0 ^ k1 ^ 0x1BD11BDAu;
    x0 += k0; x1 += k1;
#define TFR(r) { x0 += x1; x1 = (x1 << (r)) | (x1 >> (32 - (r))); x1 ^= x0; }
    TFR(13) TFR(15) TFR(26) TFR(6)   x0 += k1;  x1 += ks2 + 1u;
    TFR(17) TFR(29) TFR(16) TFR(24)  x0 += ks2; x1 += k0 + 2u;
    TFR(13) TFR(15) TFR(26) TFR(6)   x0 += k0;  x1 += k1 + 3u;
    TFR(17) TFR(29) TFR(16) TFR(24)  x0 += k1;  x1 += ks2 + 4u;
    TFR(13) TFR(15) TFR(26) TFR(6)   x0 += ks2; x1 += k0 + 5u;
#undef TFR
    return make_uint2(x0, x1);
}

// ---------------------------------------------------------------------------
// JAX threefry_partitionable=True (default in modern JAX) reproduction:
//   perm_keys[k] = threefry(key(42), counter (0, k))          [both words]
//   _, subkey    = split(perm_keys[k]) -> threefry(pk, (0,1)) [both words]
//   bits[i]      = y.x ^ y.y  with y = threefry(subkey, (0,i))
//   perm         = stable argsort(bits) applied to arange(256)
// ---------------------------------------------------------------------------
__global__ void perm_kernel(int* __restrict__ perm) {
    __shared__ unsigned sk[8][2];
    __shared__ unsigned bits[256];
    int t = threadIdx.x;
    if (t < 8) {
        uint2 pk = threefry(0u, 42u, 0u, (unsigned)t);   // perm_keys[t]
        uint2 s  = threefry(pk.x, pk.y, 0u, 1u);         // subkey = split(.)[1]
        sk[t][0] = s.x; sk[t][1] = s.y;
    }
    __syncthreads();
    for (int k = 0; k < 8; k++) {
        uint2 y = threefry(sk[k][0], sk[k][1], 0u, (unsigned)t);
        bits[t] = y.x ^ y.y;
        __syncthreads();
        unsigned mine = bits[t];
        int rank = 0;
        for (int j = 0; j < 256; j++) {
            unsigned o = bits[j];
            rank += (o < mine) || (o == mine && j < t);
        }
        perm[k * 256 + rank] = t;
        __syncthreads();
    }
}

// ---------------------------------------------------------------------------
// GEMM A: g_Genc[t*256+b][g] = x[b,t,:] . enc_Wih[g,:] + enc_bih[g]
// M=131072 (r=t*256+b), N=384, K=128. 64x64 tile, 256 thr, 4x4 microtile.
// ---------------------------------------------------------------------------
__global__ void __launch_bounds__(256) gemm_gi(const float* __restrict__ X,
                                               const float* __restrict__ W,
                                               const float* __restrict__ bias) {
    __shared__ float As[32 * 64];
    __shared__ float Bs[32 * 64];
    int tid = threadIdx.x;
    int tx = tid & 15, ty = tid >> 4;
    int rBase = blockIdx.x * 64;
    int n0 = blockIdx.y * 64;
    float acc[4][4];
#pragma unroll
    for (int i = 0; i < 4; i++)
#pragma unroll
        for (int j = 0; j < 4; j++) acc[i][j] = 0.0f;

    for (int kc = 0; kc < 4; kc++) {
        int k0 = kc * 32;
#pragma unroll
        for (int p = 0; p < 2; p++) {
            int l = tid + p * 256;
            int row = l >> 3, q = l & 7;
            int r = rBase + row;
            const float* xp = X + (((size_t)(r & 255) * 512 + (r >> 8)) << 7);
            float4 v = *(const float4*)&xp[k0 + q * 4];
            As[(q * 4 + 0) * 64 + row] = v.x;
            As[(q * 4 + 1) * 64 + row] = v.y;
            As[(q * 4 + 2) * 64 + row] = v.z;
            As[(q * 4 + 3) * 64 + row] = v.w;
        }
#pragma unroll
        for (int p = 0; p < 2; p++) {
            int l = tid + p * 256;
            int n = l >> 3, q = l & 7;
            float4 v = *(const float4*)&W[(size_t)(n0 + n) * 128 + k0 + q * 4];
            Bs[(q * 4 + 0) * 64 + n] = v.x;
            Bs[(q * 4 + 1) * 64 + n] = v.y;
            Bs[(q * 4 + 2) * 64 + n] = v.z;
            Bs[(q * 4 + 3) * 64 + n] = v.w;
        }
        __syncthreads();
#pragma unroll
        for (int kk = 0; kk < 32; kk++) {
            float4 a = *(const float4*)&As[kk * 64 + ty * 4];
            float4 b = *(const float4*)&Bs[kk * 64 + tx * 4];
            acc[0][0] = fmaf(a.x, b.x, acc[0][0]); acc[0][1] = fmaf(a.x, b.y, acc[0][1]);
            acc[0][2] = fmaf(a.x, b.z, acc[0][2]); acc[0][3] = fmaf(a.x, b.w, acc[0][3]);
            acc[1][0] = fmaf(a.y, b.x, acc[1][0]); acc[1][1] = fmaf(a.y, b.y, acc[1][1]);
            acc[1][2] = fmaf(a.y, b.z, acc[1][2]); acc[1][3] = fmaf(a.y, b.w, acc[1][3]);
            acc[2][0] = fmaf(a.z, b.x, acc[2][0]); acc[2][1] = fmaf(a.z, b.y, acc[2][1]);
            acc[2][2] = fmaf(a.z, b.z, acc[2][2]); acc[2][3] = fmaf(a.z, b.w, acc[2][3]);
            acc[3][0] = fmaf(a.w, b.x, acc[3][0]); acc[3][1] = fmaf(a.w, b.y, acc[3][1]);
            acc[3][2] = fmaf(a.w, b.z, acc[3][2]); acc[3][3] = fmaf(a.w, b.w, acc[3][3]);
        }
        __syncthreads();
    }
    float b0 = bias[n0 + tx * 4 + 0], b1 = bias[n0 + tx * 4 + 1];
    float b2 = bias[n0 + tx * 4 + 2], b3 = bias[n0 + tx * 4 + 3];
#pragma unroll
    for (int i = 0; i < 4; i++) {
        int r = rBase + ty * 4 + i;
        float4 v = make_float4(acc[i][0] + b0, acc[i][1] + b1, acc[i][2] + b2, acc[i][3] + b3);
        *(float4*)&g_Genc[(size_t)r * 384 + n0 + tx * 4] = v;
    }
}

// ---------------------------------------------------------------------------
// out-GEMM: o_i = Hdec[i] @ out_W^T + out_b ; write to output[b][511-i][:]
// ---------------------------------------------------------------------------
__global__ void __launch_bounds__(256) gemm_out(const float* __restrict__ W,
                                                const float* __restrict__ bias,
                                                float* __restrict__ out) {
    __shared__ float As[32 * 64];
    __shared__ float Bs[32 * 64];
    int tid = threadIdx.x;
    int tx = tid & 15, ty = tid >> 4;
    int rBase = blockIdx.x * 64;
    int n0 = blockIdx.y * 64;
    float acc[4][4];
#pragma unroll
    for (int i = 0; i < 4; i++)
#pragma unroll
        for (int j = 0; j < 4; j++) acc[i][j] = 0.0f;

    for (int kc = 0; kc < 4; kc++) {
        int k0 = kc * 32;
#pragma unroll
        for (int p = 0; p < 2; p++) {
            int l = tid + p * 256;
            int row = l >> 3, q = l & 7;
            int r = rBase + row;
            float4 v = *(const float4*)&g_Hdec[(size_t)r * 128 + k0 + q * 4];
            As[(q * 4 + 0) * 64 + row] = v.x;
            As[(q * 4 + 1) * 64 + row] = v.y;
            As[(q * 4 + 2) * 64 + row] = v.z;
            As[(q * 4 + 3) * 64 + row] = v.w;
        }
#pragma unroll
        for (int p = 0; p < 2; p++) {
            int l = tid + p * 256;
            int n = l >> 3, q = l & 7;
            float4 v = *(const float4*)&W[(size_t)(n0 + n) * 128 + k0 + q * 4];
            Bs[(q * 4 + 0) * 64 + n] = v.x;
            Bs[(q * 4 + 1) * 64 + n] = v.y;
            Bs[(q * 4 + 2) * 64 + n] = v.z;
            Bs[(q * 4 + 3) * 64 + n] = v.w;
        }
        __syncthreads();
#pragma unroll
        for (int kk = 0; kk < 32; kk++) {
            float4 a = *(const float4*)&As[kk * 64 + ty * 4];
            float4 b = *(const float4*)&Bs[kk * 64 + tx * 4];
            acc[0][0] = fmaf(a.x, b.x, acc[0][0]); acc[0][1] = fmaf(a.x, b.y, acc[0][1]);
            acc[0][2] = fmaf(a.x, b.z, acc[0][2]); acc[0][3] = fmaf(a.x, b.w, acc[0][3]);
            acc[1][0] = fmaf(a.y, b.x, acc[1][0]); acc[1][1] = fmaf(a.y, b.y, acc[1][1]);
            acc[1][2] = fmaf(a.y, b.z, acc[1][2]); acc[1][3] = fmaf(a.y, b.w, acc[1][3]);
            acc[2][0] = fmaf(a.z, b.x, acc[2][0]); acc[2][1] = fmaf(a.z, b.y, acc[2][1]);
            acc[2][2] = fmaf(a.z, b.z, acc[2][2]); acc[2][3] = fmaf(a.z, b.w, acc[2][3]);
            acc[3][0] = fmaf(a.w, b.x, acc[3][0]); acc[3][1] = fmaf(a.w, b.y, acc[3][1]);
            acc[3][2] = fmaf(a.w, b.z, acc[3][2]); acc[3][3] = fmaf(a.w, b.w, acc[3][3]);
        }
        __syncthreads();
    }
    float b0 = bias[n0 + tx * 4 + 0], b1 = bias[n0 + tx * 4 + 1];
    float b2 = bias[n0 + tx * 4 + 2], b3 = bias[n0 + tx * 4 + 3];
#pragma unroll
    for (int i = 0; i < 4; i++) {
        int r = rBase + ty * 4 + i;
        int is = r >> 8, bb = r & 255;
        size_t orow = (size_t)(bb * 512 + (511 - is)) * 128;
        float4 v = make_float4(acc[i][0] + b0, acc[i][1] + b1, acc[i][2] + b2, acc[i][3] + b3);
        *(float4*)&out[OFF_OUT + orow + n0 + tx * 4] = v;
    }
}

// ---------------------------------------------------------------------------
// Fold: Mf[g][j] = sum_f dec_Wih[g,f]*out_W[f,j];  bf[g] = dec_bih[g] + dec_Wih[g,:].out_b
// ---------------------------------------------------------------------------
__global__ void fold_kernel(const float* __restrict__ dWih, const float* __restrict__ outW,
                            const float* __restrict__ outb, const float* __restrict__ dbih) {
    int g = blockIdx.x, j = threadIdx.x;
    __shared__ float wrow[128];
    __shared__ float red[128];
    wrow[j] = dWih[g * 128 + j];
    __syncthreads();
    float acc = 0.0f;
#pragma unroll 8
    for (int f = 0; f < 128; f++) acc = fmaf(wrow[f], outW[f * 128 + j], acc);
    g_Mf[g * 128 + j] = acc;
    red[j] = wrow[j] * outb[j];
    __syncthreads();
    for (int s = 64; s > 0; s >>= 1) {
        if (j < s) red[j] += red[j + s];
        __syncthreads();
    }
    if (j == 0) g_bf[g] = dbih[g] + red[0];
}

// ---------------------------------------------------------------------------
// Encoder recurrence: 128 CTAs x 384 threads; 2 batch elems per CTA.
// Thread g holds Whh row g in registers.
// ---------------------------------------------------------------------------
__global__ void __launch_bounds__(384, 1) enc_kernel(const float* __restrict__ Whh,
                                                     const float* __restrict__ bhh) {
    __shared__ float h_sm[2][128];
    __shared__ float gh_sm[2][384];
    int g = threadIdx.x;
    int b0 = blockIdx.x * 2;
    float w[128];
#pragma unroll
    for (int k = 0; k < 128; k += 4) {
        float4 v = *(const float4*)&Whh[(size_t)g * 128 + k];
        w[k] = v.x; w[k + 1] = v.y; w[k + 2] = v.z; w[k + 3] = v.w;
    }
    float bg = bhh[g];
    int bb = g >> 7, j = g & 127;
    if (g < 256) h_sm[bb][j] = 0.0f;
    __syncthreads();

    for (int t = 0; t < 512; t++) {
        float gi_r = 0.f, gi_z = 0.f, gi_n = 0.f;
        if (g < 256) {
            const float* gp = g_Genc + ((size_t)t * 256 + b0 + bb) * 384;
            gi_r = gp[j]; gi_z = gp[128 + j]; gi_n = gp[256 + j];
        }
        float a0 = bg, a1 = bg;
#pragma unroll
        for (int k = 0; k < 128; k += 4) {
            float4 h0 = *(const float4*)&h_sm[0][k];
            float4 h1 = *(const float4*)&h_sm[1][k];
            a0 = fmaf(w[k], h0.x, a0);     a1 = fmaf(w[k], h1.x, a1);
            a0 = fmaf(w[k + 1], h0.y, a0); a1 = fmaf(w[k + 1], h1.y, a1);
            a0 = fmaf(w[k + 2], h0.z, a0); a1 = fmaf(w[k + 2], h1.z, a1);
            a0 = fmaf(w[k + 3], h0.w, a0); a1 = fmaf(w[k + 3], h1.w, a1);
        }
        gh_sm[0][g] = a0;
        gh_sm[1][g] = a1;
        __syncthreads();
        if (g < 256) {
            float r = sigf(gi_r + gh_sm[bb][j]);
            float z = sigf(gi_z + gh_sm[bb][128 + j]);
            float n = tanhf(gi_n + r * gh_sm[bb][256 + j]);
            h_sm[bb][j] = (1.0f - z) * n + z * h_sm[bb][j];
        }
        __syncthreads();
    }
    if (g < 256) g_Henc[(b0 + bb) * 128 + j] = h_sm[bb][j];
}

// ---------------------------------------------------------------------------
// Decoder recurrence. Mfused in regs, dec_Whh^T in smem (128x385 padded).
// Stores h_i (pre-update) to g_Hdec[i][b][:].
// ---------------------------------------------------------------------------
__global__ void __launch_bounds__(384, 1) dec_kernel(const float* __restrict__ Whh,
                                                     const float* __restrict__ bhh) {
    extern __shared__ float ds[];
    float* wT  = ds;            // 128*385 = 49280 floats
    float* hsm = ds + 49280;    // 256
    float* gis = ds + 49536;    // 768
    float* ghs = ds + 50304;    // 768
    int g = threadIdx.x;
    int b0 = blockIdx.x * 2;
    int bb = g >> 7, j = g & 127;

    float w[128];
#pragma unroll
    for (int k = 0; k < 128; k += 4) {
        float4 v = *(const float4*)&g_Mf[(size_t)g * 128 + k];
        w[k] = v.x; w[k + 1] = v.y; w[k + 2] = v.z; w[k + 3] = v.w;
    }
    float bfg = g_bf[g];
    float bhg = bhh[g];

    for (int idx = g; idx < 384 * 128; idx += 384) {
        int gg = idx >> 7, kk = idx & 127;
        wT[kk * 385 + gg] = Whh[idx];
    }
    if (g < 256) hsm[g] = g_Henc[b0 * 128 + g];
    __syncthreads();

    for (int i = 0; i < 512; i++) {
        if (g < 256) g_Hdec[((size_t)i * 256 + b0 + bb) * 128 + j] = hsm[g];
        float gi0 = bfg, gi1 = bfg, gh0 = bhg, gh1 = bhg;
#pragma unroll
        for (int k = 0; k < 128; k += 4) {
            float4 h0 = *(const float4*)&hsm[k];
            float4 h1 = *(const float4*)&hsm[128 + k];
            float wh0 = wT[(k + 0) * 385 + g];
            float wh1 = wT[(k + 1) * 385 + g];
            float wh2 = wT[(k + 2) * 385 + g];
            float wh3 = wT[(k + 3) * 385 + g];
            gi0 = fmaf(w[k], h0.x, gi0);     gi1 = fmaf(w[k], h1.x, gi1);
            gh0 = fmaf(wh0, h0.x, gh0);      gh1 = fmaf(wh0, h1.x, gh1);
            gi0 = fmaf(w[k + 1], h0.y, gi0); gi1 = fmaf(w[k + 1], h1.y, gi1);
            gh0 = fmaf(wh1, h0.y, gh0);      gh1 = fmaf(wh1, h1.y, gh1);
            gi0 = fmaf(w[k + 2], h0.z, gi0); gi1 = fmaf(w[k + 2], h1.z, gi1);
            gh0 = fmaf(wh2, h0.z, gh0);      gh1 = fmaf(wh2, h1.z, gh1);
            gi0 = fmaf(w[k + 3], h0.w, gi0); gi1 = fmaf(w[k + 3], h1.w, gi1);
            gh0 = fmaf(wh3, h0.w, gh0);      gh1 = fmaf(wh3, h1.w, gh1);
        }
        gis[g] = gi0; gis[384 + g] = gi1;
        ghs[g] = gh0; ghs[384 + g] = gh1;
        __syncthreads();
        if (g < 256) {
            int base = bb * 384;
            float r = sigf(gis[base + j] + ghs[base + j]);
            float z = sigf(gis[base + 128 + j] + ghs[base + 128 + j]);
            float n = tanhf(gis[base + 256 + j] + r * ghs[base + 256 + j]);
            hsm[g] = (1.0f - z) * n + z * hsm[g];
        }
        __syncthreads();
    }
}

// ---------------------------------------------------------------------------
// Epilogue A: cosine, h_enc copy, LN/attn/dis/z/gamma. One block per batch elem.
// ---------------------------------------------------------------------------
__device__ __forceinline__ float bsum(float v, float* red) {
    int t = threadIdx.x;
    __syncthreads();
    red[t] = v;
    __syncthreads();
    for (int s = 128; s > 0; s >>= 1) {
        if (t < s) red[t] += red[t + s];
        __syncthreads();
    }
    return red[0];
}

__global__ void __launch_bounds__(256) epiA(
    const float* __restrict__ X,
    const float* __restrict__ protos,
    const float* __restrict__ lnzw, const float* __restrict__ lnzb,
    const float* __restrict__ lnpw, const float* __restrict__ lnpb,
    const float* __restrict__ lnaw, const float* __restrict__ lnab,
    const float* __restrict__ beta,
    const float* __restrict__ e1W, const float* __restrict__ e1b,
    const float* __restrict__ e2W, const float* __restrict__ e2b,
    float* __restrict__ out) {
    int b = blockIdx.x, t = threadIdx.x;
    __shared__ float red[256];
    __shared__ float zln[128];
    __shared__ float pl[8][128];
    __shared__ float dotk[8];
    __shared__ float attnv[8];
    __shared__ float zfull[129];
    __shared__ float h1s[10];
    __shared__ float lg[4];

    // rec_cosine
    const float* a = X + (size_t)b * 65536;
    const float* o = out + OFF_OUT + (size_t)b * 65536;
    float sab = 0.f, saa = 0.f, sbb = 0.f;
    for (int i = t; i < 65536; i += 256) {
        float av = a[i], bv = o[i];
        sab = fmaf(av, bv, sab);
        saa = fmaf(av, av, saa);
        sbb = fmaf(bv, bv, sbb);
    }
    sab = bsum(sab, red);
    saa = bsum(saa, red);
    sbb = bsum(sbb, red);
    float rc = sab / (fmaxf(sqrtf(saa), 1e-8f) * fmaxf(sqrtf(sbb), 1e-8f));

    // h_enc copy + LN(z)
    float h = (t < 128) ? g_Henc[b * 128 + t] : 0.0f;
    if (t < 128) out[OFF_HENC + b * 128 + t] = h;
    float mu = bsum(h, red) * (1.0f / 128.0f);
    float d = (t < 128) ? (h - mu) : 0.0f;
    float var = bsum(d * d, red) * (1.0f / 128.0f);
    if (t < 128) zln[t] = lnzw[t] * d * rsqrtf(var + 1e-12f) + lnzb[t];

    // LN(prototypes)
    for (int k = 0; k < 8; k++) {
        float p = (t < 128) ? protos[k * 128 + t] : 0.0f;
        float pu = bsum(p, red) * (1.0f / 128.0f);
        float pd = (t < 128) ? (p - pu) : 0.0f;
        float pv = bsum(pd * pd, red) * (1.0f / 128.0f);
        if (t < 128) pl[k][t] = lnpw[t] * pd * rsqrtf(pv + 1e-12f) + lnpb[t];
    }
    __syncthreads();

    // attn = softmax(z_ln @ prot_ln^T / sqrt(H))
    for (int k = 0; k < 8; k++) {
        float pp = (t < 128) ? zln[t] * pl[k][t] : 0.0f;
        float s = bsum(pp, red);
        if (t == 0) dotk[k] = s * 0.08838834764831845f;  // 1/sqrt(128)
    }
    __syncthreads();
    if (t < 8) {
        float m = -1e30f;
        for (int kk = 0; kk < 8; kk++) m = fmaxf(m, dotk[kk]);
        float s = 0.f;
        for (int kk = 0; kk < 8; kk++) s += expf(dotk[kk] - m);
        attnv[t] = expf(dotk[t] - m) / s;
    }
    __syncthreads();

    // dis + z mean
    float zacc = 0.0f;
    for (int k = 0; k < 8; k++) {
        float v = (t < 128) ? (beta[k * 128 + t] + attnv[k] * h) : 0.0f;
        float vu = bsum(v, red) * (1.0f / 128.0f);
        float vd = (t < 128) ? (v - vu) : 0.0f;
        float vv = bsum(vd * vd, red) * (1.0f / 128.0f);
        if (t < 128) {
            float dval = lnaw[t] * vd * rsqrtf(vv + 1e-12f) + lnab[t];
            out[OFF_DIS + ((size_t)b * 8 + k) * 128 + t] = dval;
            zacc += dval;
        }
    }
    if (t < 128) {
        float zv = zacc * 0.125f;
        zfull[t] = zv;
        out[OFF_Z + (size_t)b * 129 + t] = zv;
    }
    if (t == 0) {
        zfull[128] = rc;
        out[OFF_Z + (size_t)b * 129 + 128] = rc;
    }
    __syncthreads();

    if (t < 10) {
        float acc = e1b[t];
        for (int i = 0; i < 129; i++) acc = fmaf(e1W[t * 129 + i], zfull[i], acc);
        h1s[t] = tanhf(acc);
    }
    __syncthreads();
    if (t < 4) {
        float acc = e2b[t];
        for (int i = 0; i < 10; i++) acc = fmaf(e2W[t * 10 + i], h1s[i], acc);
        lg[t] = acc;
    }
    __syncthreads();
    if (t < 4) {
        float m = fmaxf(fmaxf(lg[0], lg[1]), fmaxf(lg[2], lg[3]));
        float s = expf(lg[0] - m) + expf(lg[1] - m) + expf(lg[2] - m) + expf(lg[3] - m);
        out[OFF_GAMMA + (size_t)b * 4 + t] = expf(lg[t] - m) / s;
    }
}

// dis_perm[b,k,:] = dis[perm_k[b], k, :]
__global__ void epiB(float* __restrict__ out, const int* __restrict__ perm) {
    int b = blockIdx.x;
    for (int e = threadIdx.x; e < 1024; e += blockDim.x) {
        int k = e >> 7, j = e & 127;
        int src = perm[k * 256 + b];
        out[OFF_DISP + ((size_t)b * 8 + k) * 128 + j] =
            out[OFF_DIS + ((size_t)src * 8 + k) * 128 + j];
    }
}

// ---------------------------------------------------------------------------
extern "C" void kernel_launch(void* const* d_in, const int* in_sizes, int n_in,
                              void* d_out, int out_size) {
    const float* input   = (const float*)d_in[0];
    const float* enc_Wih = (const float*)d_in[1];
    const float* enc_Whh = (const float*)d_in[2];
    const float* enc_bih = (const float*)d_in[3];
    const float* enc_bhh = (const float*)d_in[4];
    const float* dec_Wih = (const float*)d_in[5];
    const float* dec_Whh = (const float*)d_in[6];
    const float* dec_bih = (const float*)d_in[7];
    const float* dec_bhh = (const float*)d_in[8];
    const float* out_W   = (const float*)d_in[9];
    const float* out_b   = (const float*)d_in[10];
    const float* protos  = (const float*)d_in[11];
    const float* lnz_w   = (const float*)d_in[12];
    const float* lnz_b   = (const float*)d_in[13];
    const float* lnp_w   = (const float*)d_in[14];
    const float* lnp_b   = (const float*)d_in[15];
    const float* lna_w   = (const float*)d_in[16];
    const float* lna_b   = (const float*)d_in[17];
    const float* beta    = (const float*)d_in[18];
    const float* est1_W  = (const float*)d_in[19];
    const float* est1_b  = (const float*)d_in[20];
    const float* est2_W  = (const float*)d_in[21];
    const float* est2_b  = (const float*)d_in[22];
    float* out = (float*)d_out;

    int* perm_ptr = nullptr;
    cudaGetSymbolAddress((void**)&perm_ptr, g_perm);

    cudaFuncSetAttribute(dec_kernel, cudaFuncAttributeMaxDynamicSharedMemorySize, 204288);

    // 1. Encoder input gates (time-parallel GEMM)
    gemm_gi<<<dim3(2048, 6), 256>>>(input, enc_Wih, enc_bih);
    // 2. Encoder recurrence
    enc_kernel<<<128, 384>>>(enc_Whh, enc_bhh);
    // 3. Fold output projection into decoder input weights
    fold_kernel<<<384, 128>>>(dec_Wih, out_W, out_b, dec_bih);
    // 4. Decoder recurrence (stores h_i trajectory)
    dec_kernel<<<128, 384, 204288>>>(dec_Whh, dec_bhh);
    // 5. Output projection for all 512 steps (parallel GEMM)
    gemm_out<<<dim3(2048, 2), 256>>>(out_W, out_b, out);
    // 6. JAX-exact permutations (threefry_partitionable scheme)
    perm_kernel<<<1, 256>>>(perm_ptr);
    // 7. Epilogue: cosine, LN, attention, dis, z, gamma
    epiA<<<256, 256>>>(input, protos, lnz_w, lnz_b, lnp_w, lnp_b, lna_w, lna_b,
                       beta, est1_W, est1_b, est2_W, est2_b, out);
    // 8. dis_perm gather
    epiB<<<256, 256>>>(out, perm_ptr);
}